// round 15
// baseline (speedup 1.0000x reference)
#include <cuda_runtime.h>

// Mandelbrot boundary-proximity loss. R15 = R14 (PDL pipeline, 58.2us) with
// packed f32x2 arithmetic (sm_103a FFMA2/FADD2/FMUL2 via PTX) in all hot
// loops: p1 processes its 4 points as 2 packed pairs; 2a/2b process 2
// survivors per thread packed. Each packed lane performs the IDENTICAL
// IEEE-RN operation sequence as the scalar code (mul by -1 == neg exactly),
// so classification is unchanged (rel_err must remain exactly 1.769343e-06).
// Cycle check omitted (value-neutral). Exact integer ULL sum => deterministic.

#define NMAX 8388608
#define K1 8
#define B2 40
#define P1_THREADS 256
#define P1_PTS 4
#define P2A_BLOCKS 2048
#define P2B_BLOCKS 768
#define P2_THREADS 256

typedef unsigned long long u64p;

#define FMA2(d,a,b,c) asm("fma.rn.f32x2 %0, %1, %2, %3;" : "=l"(d) : "l"(a), "l"(b), "l"(c))
#define ADD2(d,a,b)   asm("add.rn.f32x2 %0, %1, %2;"     : "=l"(d) : "l"(a), "l"(b))
#define MUL2(d,a,b)   asm("mul.rn.f32x2 %0, %1, %2;"     : "=l"(d) : "l"(a), "l"(b))

__device__ __forceinline__ u64p pk2(float lo, float hi) {
    u64p d; asm("mov.b64 %0, {%1, %2};" : "=l"(d) : "f"(lo), "f"(hi)); return d;
}
__device__ __forceinline__ void upk2(u64p d, float& lo, float& hi) {
    asm("mov.b64 {%0, %1}, %2;" : "=f"(lo), "=f"(hi) : "l"(d));
}

__device__ unsigned long long g_sum;   // zero-init at load
__device__ unsigned int g_ns1;
__device__ unsigned int g_ns2_lo;      // front bucket (|z40|^2 > 2)
__device__ unsigned int g_ns2_hi;      // back bucket
__device__ unsigned int g_done;
__device__ float4 g_st1[NMAX];         // {cr,ci,zr,zi} after iter K1
__device__ float4 g_st2[NMAX];         // {cr,ci,zr,zi} after iter B2

// ---------------------------------------------------------------- phase 1
__global__ void __launch_bounds__(P1_THREADS, 7) phase1_kernel(
    const float* __restrict__ c_real,
    const float* __restrict__ c_imag,
    int n)
{
    const int tid  = blockIdx.x * P1_THREADS + threadIdx.x;
    const int base = tid * P1_PTS;
    const int lane = threadIdx.x & 31;
    const int wid  = threadIdx.x >> 5;

    float cr[P1_PTS], ci[P1_PTS];
    bool valid[P1_PTS];

    if (base + P1_PTS - 1 < n) {
        const float4 r4 = *reinterpret_cast<const float4*>(c_real + base);
        const float4 i4 = *reinterpret_cast<const float4*>(c_imag + base);
        cr[0] = r4.x; cr[1] = r4.y; cr[2] = r4.z; cr[3] = r4.w;
        ci[0] = i4.x; ci[1] = i4.y; ci[2] = i4.z; ci[3] = i4.w;
        #pragma unroll
        for (int p = 0; p < P1_PTS; ++p) valid[p] = true;
    } else {
        #pragma unroll
        for (int p = 0; p < P1_PTS; ++p) {
            valid[p] = (base + p) < n;
            cr[p] = valid[p] ? c_real[base + p] : 10.0f;  // dummy escapes fast
            ci[p] = valid[p] ? c_imag[base + p] : 0.0f;
        }
    }

    // packed constants
    const u64p KN1    = pk2(-1.0f, -1.0f);
    const u64p KM025  = pk2(-0.25f, -0.25f);
    const u64p K025   = pk2(0.25f, 0.25f);
    const u64p K1F    = pk2(1.0f, 1.0f);
    const u64p KM7449 = pk2(-0.7449f, -0.7449f);
    const u64p K1226  = pk2(0.1226f, 0.1226f);

    u64p CR[2], CI[2], ZR[2], ZI[2];
    CR[0] = pk2(cr[0], cr[1]); CR[1] = pk2(cr[2], cr[3]);
    CI[0] = pk2(ci[0], ci[1]); CI[1] = pk2(ci[2], ci[3]);
    ZR[0] = ZR[1] = ZI[0] = ZI[1] = 0ULL;

    // ---- packed analytic in-set tests ----
    bool in_set[P1_PTS];
    #pragma unroll
    for (int q = 0; q < 2; ++q) {
        u64p C2;  MUL2(C2, CI[q], CI[q]);
        u64p XM;  ADD2(XM, CR[q], KM025);
        u64p Q;   FMA2(Q, XM, XM, C2);
        u64p QX;  ADD2(QX, Q, XM);
        u64p L1;  MUL2(L1, Q, QX);
        u64p R1;  MUL2(R1, C2, K025);
        u64p XP;  ADD2(XP, CR[q], K1F);
        u64p L2;  FMA2(L2, XP, XP, C2);
        u64p AB;  asm("and.b64 %0, %1, %2;" : "=l"(AB)
                      : "l"(CI[q]), "l"(0x7FFFFFFF7FFFFFFFULL));
        u64p AY;  ADD2(AY, AB, KM7449);
        u64p AX;  ADD2(AX, CR[q], K1226);
        u64p AY2; MUL2(AY2, AY, AY);
        u64p L3;  FMA2(L3, AX, AX, AY2);

        float l1a, l1b, r1a, r1b, l2a, l2b, l3a, l3b;
        upk2(L1, l1a, l1b); upk2(R1, r1a, r1b);
        upk2(L2, l2a, l2b); upk2(L3, l3a, l3b);
        in_set[2*q]   = (l1a < r1a) | (l2a < 0.0625f) | (l3a < 0.0081f);
        in_set[2*q+1] = (l1b < r1b) | (l2b < 0.0625f) | (l3b < 0.0081f);
    }

    bool esc[P1_PTS] = {false, false, false, false};
    float cnt[P1_PTS] = {0.0f, 0.0f, 0.0f, 0.0f};

    #pragma unroll
    for (int i = 0; i < K1; ++i) {
        #pragma unroll
        for (int q = 0; q < 2; ++q) {
            u64p NZ;  MUL2(NZ, ZI[q], KN1);          // -zi (exact)
            u64p T;   FMA2(T, ZI[q], NZ, CR[q]);     // cr - zi^2 (fused)
            u64p ZR2; FMA2(ZR2, ZR[q], ZR[q], T);
            u64p TZ;  ADD2(TZ, ZR[q], ZR[q]);
            u64p ZI2; FMA2(ZI2, TZ, ZI[q], CI[q]);
            u64p SQ;  MUL2(SQ, ZI2, ZI2);
            u64p MG;  FMA2(MG, ZR2, ZR2, SQ);
            float m0, m1; upk2(MG, m0, m1);
            esc[2*q]   |= (m0 > 4.0f);
            esc[2*q+1] |= (m1 > 4.0f);
            if (!esc[2*q])   cnt[2*q]   += 1.0f;
            if (!esc[2*q+1]) cnt[2*q+1] += 1.0f;
            ZR[q] = ZR2; ZI[q] = ZI2;
        }
    }

    float zr[P1_PTS], zi[P1_PTS];
    upk2(ZR[0], zr[0], zr[1]); upk2(ZR[1], zr[2], zr[3]);
    upk2(ZI[0], zi[0], zi[1]); upk2(ZI[1], zi[2], zi[3]);

    unsigned int dist = 0;
    unsigned int smask = 0;
    #pragma unroll
    for (int p = 0; p < P1_PTS; ++p) {
        if (valid[p]) {
            if (in_set[p])   dist += 70u;                  // iters = 100
            else if (esc[p]) dist += (unsigned int)(29.0f - cnt[p]);
            else             smask |= (1u << p);
        }
    }

    // ---- fused epilogue: one packed scan = dist reduction + compaction ----
    const unsigned int k = (unsigned int)__popc(smask);
    const unsigned int packed = (k << 24) | dist;
    unsigned int incl = packed;
    #pragma unroll
    for (int off = 1; off < 32; off <<= 1) {
        unsigned int v = __shfl_up_sync(0xFFFFFFFFu, incl, off);
        if (lane >= off) incl += v;
    }
    const unsigned int excl_cnt = (incl - packed) >> 24;

    __shared__ unsigned int warp_pack[P1_THREADS / 32];
    __shared__ unsigned int warp_cbase[P1_THREADS / 32];
    __shared__ unsigned int blk_base;
    if (lane == 31) warp_pack[wid] = incl;
    __syncthreads();

    if (threadIdx.x == 0) {
        unsigned int cnt_tot = 0, dist_tot = 0;
        #pragma unroll
        for (int w = 0; w < P1_THREADS / 32; ++w) {
            unsigned int pk = warp_pack[w];
            warp_cbase[w] = cnt_tot;
            cnt_tot  += pk >> 24;
            dist_tot += pk & 0xFFFFFFu;
        }
        blk_base = cnt_tot ? atomicAdd(&g_ns1, cnt_tot) : 0u;
        if (dist_tot) atomicAdd(&g_sum, (unsigned long long)dist_tot);
    }
    __syncthreads();

    if (smask) {
        unsigned int pos = blk_base + warp_cbase[wid] + excl_cnt;
        #pragma unroll
        for (int p = 0; p < P1_PTS; ++p)
            if (smask & (1u << p)) {
                g_st1[pos] = make_float4(cr[p], ci[p], zr[p], zi[p]);
                ++pos;
            }
    }
}

// ---------------------------------------------------------------- phase 2a
// iters K1+1..B2 (32, chunk-4 vote), 2 packed items/thread; dual-end
// partition of alive points into g_st2
__global__ void __launch_bounds__(P2_THREADS) phase2a_kernel()
{
#if __CUDA_ARCH__ >= 900
    cudaGridDependencySynchronize();   // PDL: wait for phase 1 results
#endif
    const unsigned int total  = g_ns1;
    const unsigned int stride = gridDim.x * blockDim.x;
    const int lane = threadIdx.x & 31;
    const int wid  = threadIdx.x >> 5;
    const u64p KN1 = pk2(-1.0f, -1.0f);

    unsigned int local = 0;

    for (unsigned int g = blockIdx.x * blockDim.x + threadIdx.x;
         __any_sync(0xFFFFFFFFu, 2u * g < total); g += stride) {
        const unsigned int s0 = 2u * g, s1 = 2u * g + 1u;
        const bool has0 = (s0 < total), has1 = (s1 < total);
        const float4 st0 = has0 ? g_st1[s0] : make_float4(10.f, 0.f, 10.f, 0.f);
        const float4 st1 = has1 ? g_st1[s1] : make_float4(10.f, 0.f, 10.f, 0.f);

        u64p CR = pk2(st0.x, st1.x), CI = pk2(st0.y, st1.y);
        u64p ZR = pk2(st0.z, st1.z), ZI = pk2(st0.w, st1.w);
        float cnt0 = (float)K1, cnt1 = (float)K1;
        bool esc0 = false, esc1 = false;

        #pragma unroll 1
        for (int chunk = 0; chunk < (B2 - K1) / 4; ++chunk) {
            #pragma unroll
            for (int jj = 0; jj < 4; ++jj) {
                u64p NZ;  MUL2(NZ, ZI, KN1);
                u64p T;   FMA2(T, ZI, NZ, CR);
                u64p ZR2; FMA2(ZR2, ZR, ZR, T);
                u64p TZ;  ADD2(TZ, ZR, ZR);
                u64p ZI2; FMA2(ZI2, TZ, ZI, CI);
                u64p SQ;  MUL2(SQ, ZI2, ZI2);
                u64p MG;  FMA2(MG, ZR2, ZR2, SQ);
                float m0, m1; upk2(MG, m0, m1);
                esc0 |= (m0 > 4.0f);
                esc1 |= (m1 > 4.0f);
                if (!esc0) cnt0 += 1.0f;
                if (!esc1) cnt1 += 1.0f;
                ZR = ZR2; ZI = ZI2;
            }
            if (__all_sync(0xFFFFFFFFu, esc0 & esc1)) break;
        }

        if (has0 & esc0) local += (unsigned int)fabsf(cnt0 - 29.0f);
        if (has1 & esc1) local += (unsigned int)fabsf(cnt1 - 29.0f);

        float zr0, zr1, zi0, zi1;
        upk2(ZR, zr0, zr1); upk2(ZI, zi0, zi1);

        // ---- strong iter-40 dual-end re-compaction, per item slot ----
        #pragma unroll
        for (int slot = 0; slot < 2; ++slot) {
            const bool  has = slot ? has1 : has0;
            const bool  esc = slot ? esc1 : esc0;
            const float zrv = slot ? zr1 : zr0;
            const float ziv = slot ? zi1 : zi0;
            const float crv = slot ? st1.x : st0.x;
            const float civ = slot ? st1.y : st0.y;
            const bool surv = has & !esc;                  // cnt == B2
            const float mg = fmaf(zrv, zrv, ziv * ziv);
            const bool likely_esc = surv && (mg > 2.0f);

            const unsigned int sm = __ballot_sync(0xFFFFFFFFu, surv);
            const unsigned int mA = __ballot_sync(0xFFFFFFFFu, likely_esc);
            const unsigned int mB = sm & ~mA;
            if (mA) {
                unsigned int b;
                if (lane == 0) b = atomicAdd(&g_ns2_lo, (unsigned int)__popc(mA));
                b = __shfl_sync(0xFFFFFFFFu, b, 0);
                if (likely_esc) {
                    unsigned int pos = b
                        + (unsigned int)__popc(mA & ((1u << lane) - 1u));
                    g_st2[pos] = make_float4(crv, civ, zrv, ziv);
                }
            }
            if (mB) {
                unsigned int b;
                if (lane == 0) b = atomicAdd(&g_ns2_hi, (unsigned int)__popc(mB));
                b = __shfl_sync(0xFFFFFFFFu, b, 0);
                if (surv && !likely_esc) {
                    unsigned int pos = (unsigned int)NMAX - 1u
                        - (b + (unsigned int)__popc(mB & ((1u << lane) - 1u)));
                    g_st2[pos] = make_float4(crv, civ, zrv, ziv);
                }
            }
        }
    }

    #pragma unroll
    for (int off = 16; off > 0; off >>= 1)
        local += __shfl_down_sync(0xFFFFFFFFu, local, off);

    __shared__ unsigned int warp_sums[P2_THREADS / 32];
    if (lane == 0) warp_sums[wid] = local;
    __syncthreads();

    if (wid == 0) {
        unsigned int v = (lane < P2_THREADS / 32) ? warp_sums[lane] : 0u;
        #pragma unroll
        for (int off = 4; off > 0; off >>= 1)
            v += __shfl_down_sync(0xFFFFFFFFu, v, off);
        if (lane == 0 && v)
            atomicAdd(&g_sum, (unsigned long long)v);
    }
}

// ---------------------------------------------------------------- phase 2b
// iters B2+1.. (64, overrun-clamped exactly at 100), 2 packed items/thread;
// fused finalize
__global__ void __launch_bounds__(P2_THREADS) phase2b_kernel(
    float* __restrict__ out, int n)
{
#if __CUDA_ARCH__ >= 900
    cudaGridDependencySynchronize();   // PDL: wait for phase 2a results
#endif
    const unsigned int lo = g_ns2_lo;
    const unsigned int hi = g_ns2_hi;
    const unsigned int total  = lo + hi;
    const unsigned int stride = gridDim.x * blockDim.x;
    const int lane = threadIdx.x & 31;
    const int wid  = threadIdx.x >> 5;
    const u64p KN1 = pk2(-1.0f, -1.0f);

    unsigned int local = 0;

    for (unsigned int g = blockIdx.x * blockDim.x + threadIdx.x;
         __any_sync(0xFFFFFFFFu, 2u * g < total); g += stride) {
        const unsigned int s0 = 2u * g, s1 = 2u * g + 1u;
        const bool has0 = (s0 < total), has1 = (s1 < total);
        const unsigned int j0 = (s0 < lo) ? s0 : (unsigned int)NMAX - 1u - (s0 - lo);
        const unsigned int j1 = (s1 < lo) ? s1 : (unsigned int)NMAX - 1u - (s1 - lo);
        const float4 st0 = has0 ? g_st2[j0] : make_float4(10.f, 0.f, 10.f, 0.f);
        const float4 st1 = has1 ? g_st2[j1] : make_float4(10.f, 0.f, 10.f, 0.f);

        u64p CR = pk2(st0.x, st1.x), CI = pk2(st0.y, st1.y);
        u64p ZR = pk2(st0.z, st1.z), ZI = pk2(st0.w, st1.w);
        float cnt0 = (float)B2, cnt1 = (float)B2;
        bool esc0 = false, esc1 = false;

        #pragma unroll 1
        for (int chunk = 0; chunk < 8; ++chunk) {
            #pragma unroll
            for (int jj = 0; jj < 8; ++jj) {
                u64p NZ;  MUL2(NZ, ZI, KN1);
                u64p T;   FMA2(T, ZI, NZ, CR);
                u64p ZR2; FMA2(ZR2, ZR, ZR, T);
                u64p TZ;  ADD2(TZ, ZR, ZR);
                u64p ZI2; FMA2(ZI2, TZ, ZI, CI);
                u64p SQ;  MUL2(SQ, ZI2, ZI2);
                u64p MG;  FMA2(MG, ZR2, ZR2, SQ);
                float m0, m1; upk2(MG, m0, m1);
                esc0 |= (m0 > 4.0f);
                esc1 |= (m1 > 4.0f);
                if (!esc0) cnt0 += 1.0f;
                if (!esc1) cnt1 += 1.0f;
                ZR = ZR2; ZI = ZI2;
            }
            if (__all_sync(0xFFFFFFFFu, esc0 & esc1)) break;
        }

        if (has0) local += (esc0 && cnt0 <= 99.0f)
                         ? (unsigned int)fabsf(cnt0 - 29.0f) : 70u;
        if (has1) local += (esc1 && cnt1 <= 99.0f)
                         ? (unsigned int)fabsf(cnt1 - 29.0f) : 70u;
    }

    #pragma unroll
    for (int off = 16; off > 0; off >>= 1)
        local += __shfl_down_sync(0xFFFFFFFFu, local, off);

    __shared__ unsigned int warp_sums[P2_THREADS / 32];
    if (lane == 0) warp_sums[wid] = local;
    __syncthreads();

    if (wid == 0) {
        unsigned int v = (lane < P2_THREADS / 32) ? warp_sums[lane] : 0u;
        #pragma unroll
        for (int off = 4; off > 0; off >>= 1)
            v += __shfl_down_sync(0xFFFFFFFFu, v, off);
        if (lane == 0 && v)
            atomicAdd(&g_sum, (unsigned long long)v);
    }

    // ---- last-block finalize ----
    if (threadIdx.x == 0) {
        __threadfence();
        unsigned int ticket = atomicAdd(&g_done, 1u);
        if (ticket == gridDim.x - 1u) {
            __threadfence();
            double sum = (double)g_sum;
            out[0] = (float)(sum * (0.1 / 30.0) / (double)n);
            g_sum = 0ULL;          // reset for next graph replay
            g_ns1 = 0u;
            g_ns2_lo = 0u;
            g_ns2_hi = 0u;
            g_done = 0u;
        }
    }
}

extern "C" void kernel_launch(void* const* d_in, const int* in_sizes, int n_in,
                              void* d_out, int out_size)
{
    const float* c_real = (const float*)d_in[0];
    const float* c_imag = (const float*)d_in[1];
    float* out = (float*)d_out;
    const int n = in_sizes[0];

    const int pts_per_block = P1_THREADS * P1_PTS;
    const int p1_blocks = (n + pts_per_block - 1) / pts_per_block;
    phase1_kernel<<<p1_blocks, P1_THREADS>>>(c_real, c_imag, n);

    cudaLaunchAttribute attr[1];
    attr[0].id = cudaLaunchAttributeProgrammaticStreamSerialization;
    attr[0].val.programmaticStreamSerializationAllowed = 1;

    cudaLaunchConfig_t cfg2a = {};
    cfg2a.gridDim  = dim3(P2A_BLOCKS);
    cfg2a.blockDim = dim3(P2_THREADS);
    cfg2a.attrs = attr;
    cfg2a.numAttrs = 1;
    cudaLaunchKernelEx(&cfg2a, phase2a_kernel);

    cudaLaunchConfig_t cfg2b = {};
    cfg2b.gridDim  = dim3(P2B_BLOCKS);
    cfg2b.blockDim = dim3(P2_THREADS);
    cfg2b.attrs = attr;
    cfg2b.numAttrs = 1;
    cudaLaunchKernelEx(&cfg2b, phase2b_kernel, out, n);
}

// round 16
// speedup vs baseline: 1.0398x; 1.0398x over previous
#include <cuda_runtime.h>

// Mandelbrot boundary-proximity loss. R16 = best-of hybrid:
//   phase 1 : R15's packed-f32x2 kernel (measured 34.1us, occ 99.5%).
//   phase 2a/2b: R14's scalar 1-item/thread kernels (measured ~23.3us) —
//     R15 proved 2-packed-items/thread doubles warp heterogeneity and
//     regresses the vote-exit.
// PDL between stages. Lossless continuation => identical float sequences
// (rel_err must remain exactly 1.769343e-06). Cycle check omitted
// (value-neutral). Exact integer ULL sum => deterministic.

#define NMAX 8388608
#define K1 8
#define B2 40
#define P1_THREADS 256
#define P1_PTS 4
#define P2A_BLOCKS 2048
#define P2B_BLOCKS 768
#define P2_THREADS 256

typedef unsigned long long u64p;

#define FMA2(d,a,b,c) asm("fma.rn.f32x2 %0, %1, %2, %3;" : "=l"(d) : "l"(a), "l"(b), "l"(c))
#define ADD2(d,a,b)   asm("add.rn.f32x2 %0, %1, %2;"     : "=l"(d) : "l"(a), "l"(b))
#define MUL2(d,a,b)   asm("mul.rn.f32x2 %0, %1, %2;"     : "=l"(d) : "l"(a), "l"(b))

__device__ __forceinline__ u64p pk2(float lo, float hi) {
    u64p d; asm("mov.b64 %0, {%1, %2};" : "=l"(d) : "f"(lo), "f"(hi)); return d;
}
__device__ __forceinline__ void upk2(u64p d, float& lo, float& hi) {
    asm("mov.b64 {%0, %1}, %2;" : "=f"(lo), "=f"(hi) : "l"(d));
}

__device__ unsigned long long g_sum;   // zero-init at load
__device__ unsigned int g_ns1;
__device__ unsigned int g_ns2_lo;      // front bucket (|z40|^2 > 2)
__device__ unsigned int g_ns2_hi;      // back bucket
__device__ unsigned int g_done;
__device__ float4 g_st1[NMAX];         // {cr,ci,zr,zi} after iter K1
__device__ float4 g_st2[NMAX];         // {cr,ci,zr,zi} after iter B2

// ---------------------------------------------------------------- phase 1
// packed f32x2, 4 pts/thread as 2 pairs (R15 kernel, measured 34.1us)
__global__ void __launch_bounds__(P1_THREADS, 7) phase1_kernel(
    const float* __restrict__ c_real,
    const float* __restrict__ c_imag,
    int n)
{
    const int tid  = blockIdx.x * P1_THREADS + threadIdx.x;
    const int base = tid * P1_PTS;
    const int lane = threadIdx.x & 31;
    const int wid  = threadIdx.x >> 5;

    float cr[P1_PTS], ci[P1_PTS];
    bool valid[P1_PTS];

    if (base + P1_PTS - 1 < n) {
        const float4 r4 = *reinterpret_cast<const float4*>(c_real + base);
        const float4 i4 = *reinterpret_cast<const float4*>(c_imag + base);
        cr[0] = r4.x; cr[1] = r4.y; cr[2] = r4.z; cr[3] = r4.w;
        ci[0] = i4.x; ci[1] = i4.y; ci[2] = i4.z; ci[3] = i4.w;
        #pragma unroll
        for (int p = 0; p < P1_PTS; ++p) valid[p] = true;
    } else {
        #pragma unroll
        for (int p = 0; p < P1_PTS; ++p) {
            valid[p] = (base + p) < n;
            cr[p] = valid[p] ? c_real[base + p] : 10.0f;  // dummy escapes fast
            ci[p] = valid[p] ? c_imag[base + p] : 0.0f;
        }
    }

    const u64p KN1    = pk2(-1.0f, -1.0f);
    const u64p KM025  = pk2(-0.25f, -0.25f);
    const u64p K025   = pk2(0.25f, 0.25f);
    const u64p K1F    = pk2(1.0f, 1.0f);
    const u64p KM7449 = pk2(-0.7449f, -0.7449f);
    const u64p K1226  = pk2(0.1226f, 0.1226f);

    u64p CR[2], CI[2], ZR[2], ZI[2];
    CR[0] = pk2(cr[0], cr[1]); CR[1] = pk2(cr[2], cr[3]);
    CI[0] = pk2(ci[0], ci[1]); CI[1] = pk2(ci[2], ci[3]);
    ZR[0] = ZR[1] = ZI[0] = ZI[1] = 0ULL;

    // ---- packed analytic in-set tests ----
    bool in_set[P1_PTS];
    #pragma unroll
    for (int q = 0; q < 2; ++q) {
        u64p C2;  MUL2(C2, CI[q], CI[q]);
        u64p XM;  ADD2(XM, CR[q], KM025);
        u64p Q;   FMA2(Q, XM, XM, C2);
        u64p QX;  ADD2(QX, Q, XM);
        u64p L1;  MUL2(L1, Q, QX);
        u64p R1;  MUL2(R1, C2, K025);
        u64p XP;  ADD2(XP, CR[q], K1F);
        u64p L2;  FMA2(L2, XP, XP, C2);
        u64p AB;  asm("and.b64 %0, %1, %2;" : "=l"(AB)
                      : "l"(CI[q]), "l"(0x7FFFFFFF7FFFFFFFULL));
        u64p AY;  ADD2(AY, AB, KM7449);
        u64p AX;  ADD2(AX, CR[q], K1226);
        u64p AY2; MUL2(AY2, AY, AY);
        u64p L3;  FMA2(L3, AX, AX, AY2);

        float l1a, l1b, r1a, r1b, l2a, l2b, l3a, l3b;
        upk2(L1, l1a, l1b); upk2(R1, r1a, r1b);
        upk2(L2, l2a, l2b); upk2(L3, l3a, l3b);
        in_set[2*q]   = (l1a < r1a) | (l2a < 0.0625f) | (l3a < 0.0081f);
        in_set[2*q+1] = (l1b < r1b) | (l2b < 0.0625f) | (l3b < 0.0081f);
    }

    bool esc[P1_PTS] = {false, false, false, false};
    float cnt[P1_PTS] = {0.0f, 0.0f, 0.0f, 0.0f};

    #pragma unroll
    for (int i = 0; i < K1; ++i) {
        #pragma unroll
        for (int q = 0; q < 2; ++q) {
            u64p NZ;  MUL2(NZ, ZI[q], KN1);          // -zi (exact)
            u64p T;   FMA2(T, ZI[q], NZ, CR[q]);     // cr - zi^2 (fused)
            u64p ZR2; FMA2(ZR2, ZR[q], ZR[q], T);
            u64p TZ;  ADD2(TZ, ZR[q], ZR[q]);
            u64p ZI2; FMA2(ZI2, TZ, ZI[q], CI[q]);
            u64p SQ;  MUL2(SQ, ZI2, ZI2);
            u64p MG;  FMA2(MG, ZR2, ZR2, SQ);
            float m0, m1; upk2(MG, m0, m1);
            esc[2*q]   |= (m0 > 4.0f);
            esc[2*q+1] |= (m1 > 4.0f);
            if (!esc[2*q])   cnt[2*q]   += 1.0f;
            if (!esc[2*q+1]) cnt[2*q+1] += 1.0f;
            ZR[q] = ZR2; ZI[q] = ZI2;
        }
    }

    float zr[P1_PTS], zi[P1_PTS];
    upk2(ZR[0], zr[0], zr[1]); upk2(ZR[1], zr[2], zr[3]);
    upk2(ZI[0], zi[0], zi[1]); upk2(ZI[1], zi[2], zi[3]);

    unsigned int dist = 0;
    unsigned int smask = 0;
    #pragma unroll
    for (int p = 0; p < P1_PTS; ++p) {
        if (valid[p]) {
            if (in_set[p])   dist += 70u;                  // iters = 100
            else if (esc[p]) dist += (unsigned int)(29.0f - cnt[p]);
            else             smask |= (1u << p);
        }
    }

    // ---- fused epilogue: one packed scan = dist reduction + compaction ----
    const unsigned int k = (unsigned int)__popc(smask);
    const unsigned int packed = (k << 24) | dist;
    unsigned int incl = packed;
    #pragma unroll
    for (int off = 1; off < 32; off <<= 1) {
        unsigned int v = __shfl_up_sync(0xFFFFFFFFu, incl, off);
        if (lane >= off) incl += v;
    }
    const unsigned int excl_cnt = (incl - packed) >> 24;

    __shared__ unsigned int warp_pack[P1_THREADS / 32];
    __shared__ unsigned int warp_cbase[P1_THREADS / 32];
    __shared__ unsigned int blk_base;
    if (lane == 31) warp_pack[wid] = incl;
    __syncthreads();

    if (threadIdx.x == 0) {
        unsigned int cnt_tot = 0, dist_tot = 0;
        #pragma unroll
        for (int w = 0; w < P1_THREADS / 32; ++w) {
            unsigned int pk = warp_pack[w];
            warp_cbase[w] = cnt_tot;
            cnt_tot  += pk >> 24;
            dist_tot += pk & 0xFFFFFFu;
        }
        blk_base = cnt_tot ? atomicAdd(&g_ns1, cnt_tot) : 0u;
        if (dist_tot) atomicAdd(&g_sum, (unsigned long long)dist_tot);
    }
    __syncthreads();

    if (smask) {
        unsigned int pos = blk_base + warp_cbase[wid] + excl_cnt;
        #pragma unroll
        for (int p = 0; p < P1_PTS; ++p)
            if (smask & (1u << p)) {
                g_st1[pos] = make_float4(cr[p], ci[p], zr[p], zi[p]);
                ++pos;
            }
    }
}

// ---------------------------------------------------------------- phase 2a
// scalar, 1 item/thread (R14 kernel): iters K1+1..B2 (chunk-4 vote);
// dual-end partition of alive points into g_st2
__global__ void __launch_bounds__(P2_THREADS) phase2a_kernel()
{
#if __CUDA_ARCH__ >= 900
    cudaGridDependencySynchronize();   // PDL: wait for phase 1 results
#endif
    const unsigned int total  = g_ns1;
    const unsigned int stride = gridDim.x * blockDim.x;
    const int lane = threadIdx.x & 31;
    const int wid  = threadIdx.x >> 5;

    unsigned int local = 0;

    for (unsigned int s = blockIdx.x * blockDim.x + threadIdx.x;
         __any_sync(0xFFFFFFFFu, s < total); s += stride) {
        const bool has = (s < total);
        const float4 st = has ? g_st1[s]
                              : make_float4(10.0f, 0.0f, 10.0f, 0.0f);
        const float cr = st.x, ci = st.y;
        float zr = st.z, zi = st.w;
        float cnt = (float)K1;
        bool esc = false;

        #pragma unroll 1
        for (int chunk = 0; chunk < (B2 - K1) / 4; ++chunk) {
            #pragma unroll
            for (int jj = 0; jj < 4; ++jj) {
                float t   = fmaf(zi, -zi, cr);
                float zr2 = fmaf(zr,  zr, t);
                float zi2 = fmaf(zr + zr, zi, ci);
                float mag = fmaf(zr2, zr2, zi2 * zi2);
                esc |= (mag > 4.0f);
                if (!esc) cnt += 1.0f;
                zr = zr2; zi = zi2;
            }
            if (__all_sync(0xFFFFFFFFu, esc)) break;
        }

        if (has & esc) local += (unsigned int)fabsf(cnt - 29.0f);

        // ---- strong iter-40 dual-end re-compaction ----
        const bool surv = has & !esc;                      // cnt == B2
        const float magf = fmaf(zr, zr, zi * zi);
        const bool likely_esc = surv && (magf > 2.0f);

        const unsigned int smaskv = __ballot_sync(0xFFFFFFFFu, surv);
        const unsigned int maskA  = __ballot_sync(0xFFFFFFFFu, likely_esc);
        const unsigned int maskB  = smaskv & ~maskA;
        if (maskA) {
            unsigned int b;
            if (lane == 0) b = atomicAdd(&g_ns2_lo, (unsigned int)__popc(maskA));
            b = __shfl_sync(0xFFFFFFFFu, b, 0);
            if (likely_esc) {
                unsigned int pos = b
                    + (unsigned int)__popc(maskA & ((1u << lane) - 1u));
                g_st2[pos] = make_float4(cr, ci, zr, zi);
            }
        }
        if (maskB) {
            unsigned int b;
            if (lane == 0) b = atomicAdd(&g_ns2_hi, (unsigned int)__popc(maskB));
            b = __shfl_sync(0xFFFFFFFFu, b, 0);
            if (surv && !likely_esc) {
                unsigned int pos = (unsigned int)NMAX - 1u
                    - (b + (unsigned int)__popc(maskB & ((1u << lane) - 1u)));
                g_st2[pos] = make_float4(cr, ci, zr, zi);
            }
        }
    }

    #pragma unroll
    for (int off = 16; off > 0; off >>= 1)
        local += __shfl_down_sync(0xFFFFFFFFu, local, off);

    __shared__ unsigned int warp_sums[P2_THREADS / 32];
    if (lane == 0) warp_sums[wid] = local;
    __syncthreads();

    if (wid == 0) {
        unsigned int v = (lane < P2_THREADS / 32) ? warp_sums[lane] : 0u;
        #pragma unroll
        for (int off = 4; off > 0; off >>= 1)
            v += __shfl_down_sync(0xFFFFFFFFu, v, off);
        if (lane == 0 && v)
            atomicAdd(&g_sum, (unsigned long long)v);
    }
}

// ---------------------------------------------------------------- phase 2b
// scalar, 1 item/thread (R14 kernel): iters B2+1.. (overrun-clamped at 100);
// fused finalize
__global__ void __launch_bounds__(P2_THREADS) phase2b_kernel(
    float* __restrict__ out, int n)
{
#if __CUDA_ARCH__ >= 900
    cudaGridDependencySynchronize();   // PDL: wait for phase 2a results
#endif
    const unsigned int lo = g_ns2_lo;
    const unsigned int hi = g_ns2_hi;
    const unsigned int total  = lo + hi;
    const unsigned int stride = gridDim.x * blockDim.x;
    const int lane = threadIdx.x & 31;
    const int wid  = threadIdx.x >> 5;

    unsigned int local = 0;

    for (unsigned int s = blockIdx.x * blockDim.x + threadIdx.x;
         __any_sync(0xFFFFFFFFu, s < total); s += stride) {
        const bool has = (s < total);
        const unsigned int j = (s < lo) ? s
                             : (unsigned int)NMAX - 1u - (s - lo);
        const float4 st = has ? g_st2[j]
                              : make_float4(10.0f, 0.0f, 10.0f, 0.0f);
        const float cr = st.x, ci = st.y;
        float zr = st.z, zi = st.w;
        float cnt = (float)B2;
        bool esc = false;

        #pragma unroll 1
        for (int chunk = 0; chunk < 8; ++chunk) {
            #pragma unroll
            for (int jj = 0; jj < 8; ++jj) {
                float t   = fmaf(zi, -zi, cr);
                float zr2 = fmaf(zr,  zr, t);
                float zi2 = fmaf(zr + zr, zi, ci);
                float mag = fmaf(zr2, zr2, zi2 * zi2);
                esc |= (mag > 4.0f);
                if (!esc) cnt += 1.0f;
                zr = zr2; zi = zi2;
            }
            if (__all_sync(0xFFFFFFFFu, esc)) break;
        }

        if (has) {
            // escape at iter cnt+1 <= 100 -> |cnt-29|; else (cnt>99) -> 70,
            // exactly matching the reference's 100-iteration cap.
            unsigned int d = (esc && cnt <= 99.0f)
                           ? (unsigned int)fabsf(cnt - 29.0f) : 70u;
            local += d;
        }
    }

    #pragma unroll
    for (int off = 16; off > 0; off >>= 1)
        local += __shfl_down_sync(0xFFFFFFFFu, local, off);

    __shared__ unsigned int warp_sums[P2_THREADS / 32];
    if (lane == 0) warp_sums[wid] = local;
    __syncthreads();

    if (wid == 0) {
        unsigned int v = (lane < P2_THREADS / 32) ? warp_sums[lane] : 0u;
        #pragma unroll
        for (int off = 4; off > 0; off >>= 1)
            v += __shfl_down_sync(0xFFFFFFFFu, v, off);
        if (lane == 0 && v)
            atomicAdd(&g_sum, (unsigned long long)v);
    }

    // ---- last-block finalize ----
    if (threadIdx.x == 0) {
        __threadfence();
        unsigned int ticket = atomicAdd(&g_done, 1u);
        if (ticket == gridDim.x - 1u) {
            __threadfence();
            double sum = (double)g_sum;
            out[0] = (float)(sum * (0.1 / 30.0) / (double)n);
            g_sum = 0ULL;          // reset for next graph replay
            g_ns1 = 0u;
            g_ns2_lo = 0u;
            g_ns2_hi = 0u;
            g_done = 0u;
        }
    }
}

extern "C" void kernel_launch(void* const* d_in, const int* in_sizes, int n_in,
                              void* d_out, int out_size)
{
    const float* c_real = (const float*)d_in[0];
    const float* c_imag = (const float*)d_in[1];
    float* out = (float*)d_out;
    const int n = in_sizes[0];

    const int pts_per_block = P1_THREADS * P1_PTS;
    const int p1_blocks = (n + pts_per_block - 1) / pts_per_block;
    phase1_kernel<<<p1_blocks, P1_THREADS>>>(c_real, c_imag, n);

    cudaLaunchAttribute attr[1];
    attr[0].id = cudaLaunchAttributeProgrammaticStreamSerialization;
    attr[0].val.programmaticStreamSerializationAllowed = 1;

    cudaLaunchConfig_t cfg2a = {};
    cfg2a.gridDim  = dim3(P2A_BLOCKS);
    cfg2a.blockDim = dim3(P2_THREADS);
    cfg2a.attrs = attr;
    cfg2a.numAttrs = 1;
    cudaLaunchKernelEx(&cfg2a, phase2a_kernel);

    cudaLaunchConfig_t cfg2b = {};
    cfg2b.gridDim  = dim3(P2B_BLOCKS);
    cfg2b.blockDim = dim3(P2_THREADS);
    cfg2b.attrs = attr;
    cfg2b.numAttrs = 1;
    cudaLaunchKernelEx(&cfg2b, phase2b_kernel, out, n);
}